// round 1
// baseline (speedup 1.0000x reference)
#include <cuda_runtime.h>
#include <math.h>

#define N_NODES 500000
#define N_EDGES 5000000

// ---------------- scratch (device globals: allocation-free) ----------------
__device__ float g_H  [N_NODES * 16];   // projected features (messages)
__device__ float g_AGG[N_NODES * 16];   // scatter-add accumulator
__device__ float g_X1 [N_NODES * 16];   // layer-1 output
__device__ float g_X2 [N_NODES * 16];   // layer-2 output
__device__ int   g_SRC[N_EDGES];
__device__ int   g_DST[N_EDGES];
__device__ int   g_IS64;

// ---------------- dtype detection + index canonicalization ----------------
// JAX without x64 demotes int64 -> int32. Detect which layout we got:
// if the buffer is int64 (values < 2^31), every odd int32 word is 0.
__global__ void detect_kernel(const int* __restrict__ p) {
    if (blockIdx.x == 0 && threadIdx.x == 0) {
        int is64 = 1;
        #pragma unroll 1
        for (int i = 0; i < 64; i++) {
            if (p[2 * i + 1] != 0) { is64 = 0; break; }
        }
        g_IS64 = is64;
    }
}

__global__ void convert_kernel(const void* __restrict__ ei) {
    int e = blockIdx.x * blockDim.x + threadIdx.x;
    if (e >= N_EDGES) return;
    if (g_IS64) {
        const long long* p = (const long long*)ei;
        g_SRC[e] = (int)p[e];
        g_DST[e] = (int)p[(size_t)N_EDGES + e];
    } else {
        const int* p = (const int*)ei;
        g_SRC[e] = p[e];
        g_DST[e] = p[N_EDGES + e];
    }
}

// ---------------- layer 1: project (din=3) ----------------
__global__ void pre_kernel(const float* __restrict__ x,
                           const float* __restrict__ pw,
                           const float* __restrict__ pb) {
    __shared__ float sw[9], sb[3];
    int t = threadIdx.x;
    if (t < 9) sw[t] = pw[t];
    if (t < 3) sb[t] = pb[t];
    __syncthreads();
    int i = blockIdx.x * blockDim.x + t;
    if (i >= N_NODES) return;
    float x0 = x[3 * i + 0], x1 = x[3 * i + 1], x2 = x[3 * i + 2];
    #pragma unroll
    for (int j = 0; j < 3; j++) {
        float h = fmaf(x0, sw[j], fmaf(x1, sw[3 + j], fmaf(x2, sw[6 + j], sb[j])));
        g_H[3 * i + j] = fmaxf(h, 0.f);
    }
}

// ---------------- edge scatter: din=3 ----------------
__global__ void edge3_kernel() {
    int e = blockIdx.x * blockDim.x + threadIdx.x;
    if (e >= N_EDGES) return;
    int s = g_SRC[e], d = g_DST[e];
    float h0 = g_H[3 * s + 0];
    float h1 = g_H[3 * s + 1];
    float h2 = g_H[3 * s + 2];
    float* a = g_AGG + 3 * (size_t)d;
    atomicAdd(a + 0, h0);
    atomicAdd(a + 1, h1);
    atomicAdd(a + 2, h2);
}

// ---------------- edge scatter: din=16 ----------------
__global__ void edge16_kernel() {
    int e = blockIdx.x * blockDim.x + threadIdx.x;
    if (e >= N_EDGES) return;
    int s = g_SRC[e], d = g_DST[e];
    const float4* hv = (const float4*)(g_H + 16 * (size_t)s);
    float4 v0 = hv[0], v1 = hv[1], v2 = hv[2], v3 = hv[3];
    float* a = g_AGG + 16 * (size_t)d;
    atomicAdd(a + 0,  v0.x); atomicAdd(a + 1,  v0.y);
    atomicAdd(a + 2,  v0.z); atomicAdd(a + 3,  v0.w);
    atomicAdd(a + 4,  v1.x); atomicAdd(a + 5,  v1.y);
    atomicAdd(a + 6,  v1.z); atomicAdd(a + 7,  v1.w);
    atomicAdd(a + 8,  v2.x); atomicAdd(a + 9,  v2.y);
    atomicAdd(a + 10, v2.z); atomicAdd(a + 11, v2.w);
    atomicAdd(a + 12, v3.x); atomicAdd(a + 13, v3.y);
    atomicAdd(a + 14, v3.z); atomicAdd(a + 15, v3.w);
}

// ---------------- node update layer 1 (din=3, dout=16) + project-2 fused --
__global__ void node1_kernel(const float* __restrict__ x,
                             const float* __restrict__ lw,
                             const float* __restrict__ lb,
                             const float* __restrict__ rw,
                             const float* __restrict__ pw,
                             const float* __restrict__ pb) {
    __shared__ float s_lw[48], s_rw[48], s_lb[16], s_pw[256], s_pb[16];
    int t = threadIdx.x;
    if (t < 48) { s_lw[t] = lw[t]; s_rw[t] = rw[t]; }
    if (t < 16) { s_lb[t] = lb[t]; s_pb[t] = pb[t]; }
    if (t < 256) s_pw[t] = pw[t];
    __syncthreads();
    int i = blockIdx.x * blockDim.x + t;
    if (i >= N_NODES) return;

    float a[3], xr[3];
    #pragma unroll
    for (int k = 0; k < 3; k++) { a[k] = g_AGG[3 * i + k]; xr[k] = x[3 * i + k]; }

    float acc[16];
    #pragma unroll
    for (int j = 0; j < 16; j++) acc[j] = s_lb[j];
    #pragma unroll
    for (int k = 0; k < 3; k++) {
        #pragma unroll
        for (int j = 0; j < 16; j++)
            acc[j] = fmaf(a[k], s_lw[k * 16 + j], fmaf(xr[k], s_rw[k * 16 + j], acc[j]));
    }
    #pragma unroll
    for (int j = 0; j < 16; j++) acc[j] = fmaxf(acc[j], 0.f);

    float4* xo = (float4*)(g_X1 + 16 * (size_t)i);
    xo[0] = make_float4(acc[0], acc[1], acc[2], acc[3]);
    xo[1] = make_float4(acc[4], acc[5], acc[6], acc[7]);
    xo[2] = make_float4(acc[8], acc[9], acc[10], acc[11]);
    xo[3] = make_float4(acc[12], acc[13], acc[14], acc[15]);

    // fused project for layer 2
    float h[16];
    #pragma unroll
    for (int j = 0; j < 16; j++) h[j] = s_pb[j];
    #pragma unroll
    for (int k = 0; k < 16; k++) {
        #pragma unroll
        for (int j = 0; j < 16; j++)
            h[j] = fmaf(acc[k], s_pw[k * 16 + j], h[j]);
    }
    float4* ho = (float4*)(g_H + 16 * (size_t)i);
    ho[0] = make_float4(fmaxf(h[0], 0.f),  fmaxf(h[1], 0.f),  fmaxf(h[2], 0.f),  fmaxf(h[3], 0.f));
    ho[1] = make_float4(fmaxf(h[4], 0.f),  fmaxf(h[5], 0.f),  fmaxf(h[6], 0.f),  fmaxf(h[7], 0.f));
    ho[2] = make_float4(fmaxf(h[8], 0.f),  fmaxf(h[9], 0.f),  fmaxf(h[10], 0.f), fmaxf(h[11], 0.f));
    ho[3] = make_float4(fmaxf(h[12], 0.f), fmaxf(h[13], 0.f), fmaxf(h[14], 0.f), fmaxf(h[15], 0.f));
}

// ---------------- node update layer 2 (16->16) + project-3 fused ----------
__global__ void node2_kernel(const float* __restrict__ lw,
                             const float* __restrict__ lb,
                             const float* __restrict__ rw,
                             const float* __restrict__ pw,
                             const float* __restrict__ pb) {
    __shared__ float s_lw[256], s_rw[256], s_lb[16], s_pw[256], s_pb[16];
    int t = threadIdx.x;
    if (t < 256) { s_lw[t] = lw[t]; s_rw[t] = rw[t]; s_pw[t] = pw[t]; }
    if (t < 16)  { s_lb[t] = lb[t]; s_pb[t] = pb[t]; }
    __syncthreads();
    int i = blockIdx.x * blockDim.x + t;
    if (i >= N_NODES) return;

    const float4* av = (const float4*)(g_AGG + 16 * (size_t)i);
    const float4* xv = (const float4*)(g_X1 + 16 * (size_t)i);
    float4 A[4] = {av[0], av[1], av[2], av[3]};
    float4 X[4] = {xv[0], xv[1], xv[2], xv[3]};
    float a[16] = {A[0].x, A[0].y, A[0].z, A[0].w, A[1].x, A[1].y, A[1].z, A[1].w,
                   A[2].x, A[2].y, A[2].z, A[2].w, A[3].x, A[3].y, A[3].z, A[3].w};
    float xr[16] = {X[0].x, X[0].y, X[0].z, X[0].w, X[1].x, X[1].y, X[1].z, X[1].w,
                    X[2].x, X[2].y, X[2].z, X[2].w, X[3].x, X[3].y, X[3].z, X[3].w};

    float acc[16];
    #pragma unroll
    for (int j = 0; j < 16; j++) acc[j] = s_lb[j];
    #pragma unroll
    for (int k = 0; k < 16; k++) {
        #pragma unroll
        for (int j = 0; j < 16; j++)
            acc[j] = fmaf(a[k], s_lw[k * 16 + j], fmaf(xr[k], s_rw[k * 16 + j], acc[j]));
    }
    #pragma unroll
    for (int j = 0; j < 16; j++) acc[j] = fmaxf(acc[j], 0.f);

    float4* xo = (float4*)(g_X2 + 16 * (size_t)i);
    xo[0] = make_float4(acc[0], acc[1], acc[2], acc[3]);
    xo[1] = make_float4(acc[4], acc[5], acc[6], acc[7]);
    xo[2] = make_float4(acc[8], acc[9], acc[10], acc[11]);
    xo[3] = make_float4(acc[12], acc[13], acc[14], acc[15]);

    float h[16];
    #pragma unroll
    for (int j = 0; j < 16; j++) h[j] = s_pb[j];
    #pragma unroll
    for (int k = 0; k < 16; k++) {
        #pragma unroll
        for (int j = 0; j < 16; j++)
            h[j] = fmaf(acc[k], s_pw[k * 16 + j], h[j]);
    }
    float4* ho = (float4*)(g_H + 16 * (size_t)i);
    ho[0] = make_float4(fmaxf(h[0], 0.f),  fmaxf(h[1], 0.f),  fmaxf(h[2], 0.f),  fmaxf(h[3], 0.f));
    ho[1] = make_float4(fmaxf(h[4], 0.f),  fmaxf(h[5], 0.f),  fmaxf(h[6], 0.f),  fmaxf(h[7], 0.f));
    ho[2] = make_float4(fmaxf(h[8], 0.f),  fmaxf(h[9], 0.f),  fmaxf(h[10], 0.f), fmaxf(h[11], 0.f));
    ho[3] = make_float4(fmaxf(h[12], 0.f), fmaxf(h[13], 0.f), fmaxf(h[14], 0.f), fmaxf(h[15], 0.f));
}

// ---------------- node update layer 3 (16->1) + sigmoid ----------------
__global__ void node3_kernel(const float* __restrict__ lw,
                             const float* __restrict__ lb,
                             const float* __restrict__ rw,
                             float* __restrict__ out) {
    __shared__ float s_lw[16], s_rw[16], s_lb;
    int t = threadIdx.x;
    if (t < 16) { s_lw[t] = lw[t]; s_rw[t] = rw[t]; }
    if (t == 0) s_lb = lb[0];
    __syncthreads();
    int i = blockIdx.x * blockDim.x + t;
    if (i >= N_NODES) return;

    const float4* av = (const float4*)(g_AGG + 16 * (size_t)i);
    const float4* xv = (const float4*)(g_X2 + 16 * (size_t)i);
    float z = s_lb;
    #pragma unroll
    for (int q = 0; q < 4; q++) {
        float4 A = av[q], X = xv[q];
        z = fmaf(A.x, s_lw[4 * q + 0], z);
        z = fmaf(A.y, s_lw[4 * q + 1], z);
        z = fmaf(A.z, s_lw[4 * q + 2], z);
        z = fmaf(A.w, s_lw[4 * q + 3], z);
        z = fmaf(X.x, s_rw[4 * q + 0], z);
        z = fmaf(X.y, s_rw[4 * q + 1], z);
        z = fmaf(X.z, s_rw[4 * q + 2], z);
        z = fmaf(X.w, s_rw[4 * q + 3], z);
    }
    out[i] = 1.f / (1.f + expf(-z));
}

// ---------------- launch ----------------
extern "C" void kernel_launch(void* const* d_in, const int* in_sizes, int n_in,
                              void* d_out, int out_size) {
    const float* x   = (const float*)d_in[0];
    const void*  ei  = d_in[1];
    const float* p1w = (const float*)d_in[2];
    const float* p1b = (const float*)d_in[3];
    const float* l1w = (const float*)d_in[4];
    const float* l1b = (const float*)d_in[5];
    const float* r1w = (const float*)d_in[6];
    const float* p2w = (const float*)d_in[7];
    const float* p2b = (const float*)d_in[8];
    const float* l2w = (const float*)d_in[9];
    const float* l2b = (const float*)d_in[10];
    const float* r2w = (const float*)d_in[11];
    const float* p3w = (const float*)d_in[12];
    const float* p3b = (const float*)d_in[13];
    const float* l3w = (const float*)d_in[14];
    const float* l3b = (const float*)d_in[15];
    const float* r3w = (const float*)d_in[16];
    float* out = (float*)d_out;

    void* aggp = nullptr;
    cudaGetSymbolAddress(&aggp, g_AGG);

    const int TB = 256;
    int gridE = (N_EDGES + TB - 1) / TB;
    int gridN = (N_NODES + TB - 1) / TB;

    detect_kernel<<<1, 32>>>((const int*)ei);
    convert_kernel<<<gridE, TB>>>(ei);

    // layer 1
    pre_kernel<<<gridN, TB>>>(x, p1w, p1b);
    cudaMemsetAsync(aggp, 0, (size_t)N_NODES * 3 * sizeof(float));
    edge3_kernel<<<gridE, TB>>>();
    node1_kernel<<<gridN, TB>>>(x, l1w, l1b, r1w, p2w, p2b);

    // layer 2
    cudaMemsetAsync(aggp, 0, (size_t)N_NODES * 16 * sizeof(float));
    edge16_kernel<<<gridE, TB>>>();
    node2_kernel<<<gridN, TB>>>(l2w, l2b, r2w, p3w, p3b);

    // layer 3
    cudaMemsetAsync(aggp, 0, (size_t)N_NODES * 16 * sizeof(float));
    edge16_kernel<<<gridE, TB>>>();
    node3_kernel<<<gridN, TB>>>(l3w, l3b, r3w, out);
}

// round 3
// speedup vs baseline: 1.5864x; 1.5864x over previous
#include <cuda_runtime.h>
#include <math.h>

#define N_NODES 500000
#define N_EDGES 5000000

#define SCAN_T 256
#define SCAN_I 8
#define SEG (SCAN_T * SCAN_I)                 // 2048
#define NSEG ((N_NODES + SEG - 1) / SEG)      // 245

// ---------------- scratch (device globals: allocation-free) ----------------
__device__ float g_HP [N_NODES * 4];    // layer-1 projected features (padded to 4)
__device__ float g_H  [N_NODES * 16];   // layer-2 messages
__device__ float g_H2 [N_NODES * 16];   // layer-3 messages
__device__ float g_X1 [N_NODES * 16];   // layer-1 output
__device__ float g_X2 [N_NODES * 16];   // layer-2 output
__device__ int   g_SRC[N_EDGES];
__device__ int   g_DST[N_EDGES];
__device__ int   g_CSR[N_EDGES];        // src indices sorted by dst
__device__ int   g_ROW[N_NODES + 1];    // CSR row offsets
__device__ int   g_DEG[N_NODES];
__device__ int   g_CNT[N_NODES];
__device__ int   g_BSUM[NSEG];
__device__ int   g_BOFF[NSEG];
__device__ int   g_IS64;

// ---------------- index dtype detection ----------------
__global__ void detect_kernel(const int* __restrict__ p) {
    if (threadIdx.x == 0) {
        int is64 = 1;
        #pragma unroll 1
        for (int i = 0; i < 64; i++)
            if (p[2 * i + 1] != 0) { is64 = 0; break; }
        g_IS64 = is64;
    }
}

// convert indices to int32 AND histogram degrees of dst
__global__ void conv_hist_kernel(const void* __restrict__ ei) {
    int e = blockIdx.x * blockDim.x + threadIdx.x;
    if (e >= N_EDGES) return;
    int s, d;
    if (g_IS64) {
        const long long* p = (const long long*)ei;
        s = (int)p[e];
        d = (int)p[(size_t)N_EDGES + e];
    } else {
        const int* p = (const int*)ei;
        s = p[e];
        d = p[N_EDGES + e];
    }
    g_SRC[e] = s;
    g_DST[e] = d;
    atomicAdd(&g_DEG[d], 1);
}

// ---------------- exclusive scan of g_DEG -> g_ROW (3 passes) ----------------
__global__ void scan1_kernel() {          // per-segment reduce
    __shared__ int sm[SCAN_T];
    int t = threadIdx.x;
    int base = blockIdx.x * SEG + t * SCAN_I;
    int sum = 0;
    #pragma unroll
    for (int k = 0; k < SCAN_I; k++) {
        int i = base + k;
        if (i < N_NODES) sum += g_DEG[i];
    }
    sm[t] = sum;
    __syncthreads();
    for (int off = SCAN_T / 2; off > 0; off >>= 1) {
        if (t < off) sm[t] += sm[t + off];
        __syncthreads();
    }
    if (t == 0) g_BSUM[blockIdx.x] = sm[0];
}

__global__ void scan2_kernel() {          // single-block scan of segment sums
    __shared__ int sm[SCAN_T];
    int t = threadIdx.x;
    int v = (t < NSEG) ? g_BSUM[t] : 0;
    sm[t] = v;
    __syncthreads();
    for (int off = 1; off < SCAN_T; off <<= 1) {
        int x = (t >= off) ? sm[t - off] : 0;
        __syncthreads();
        sm[t] += x;
        __syncthreads();
    }
    if (t < NSEG) g_BOFF[t] = sm[t] - v;   // exclusive
    if (t == 0) g_ROW[N_NODES] = N_EDGES;
}

__global__ void scan3_kernel() {          // write exclusive prefix into g_ROW
    __shared__ int sm[SCAN_T];
    int t = threadIdx.x;
    int base = blockIdx.x * SEG + t * SCAN_I;
    int deg[SCAN_I];
    int tsum = 0;
    #pragma unroll
    for (int k = 0; k < SCAN_I; k++) {
        int i = base + k;
        deg[k] = (i < N_NODES) ? g_DEG[i] : 0;
        tsum += deg[k];
    }
    sm[t] = tsum;
    __syncthreads();
    for (int off = 1; off < SCAN_T; off <<= 1) {
        int x = (t >= off) ? sm[t - off] : 0;
        __syncthreads();
        sm[t] += x;
        __syncthreads();
    }
    int run = g_BOFF[blockIdx.x] + sm[t] - tsum;
    #pragma unroll
    for (int k = 0; k < SCAN_I; k++) {
        int i = base + k;
        if (i < N_NODES) g_ROW[i] = run;
        run += deg[k];
    }
}

__global__ void fill_kernel() {
    int e = blockIdx.x * blockDim.x + threadIdx.x;
    if (e >= N_EDGES) return;
    int s = g_SRC[e], d = g_DST[e];
    int pos = g_ROW[d] + atomicAdd(&g_CNT[d], 1);
    g_CSR[pos] = s;
}

// ---------------- layer-1 projection (din=3), padded to stride 4 ----------
__global__ void pre_kernel(const float* __restrict__ x,
                           const float* __restrict__ pw,
                           const float* __restrict__ pb) {
    __shared__ float sw[9], sb[3];
    int t = threadIdx.x;
    if (t < 9) sw[t] = pw[t];
    if (t < 3) sb[t] = pb[t];
    __syncthreads();
    int i = blockIdx.x * blockDim.x + t;
    if (i >= N_NODES) return;
    float x0 = x[3 * i + 0], x1 = x[3 * i + 1], x2 = x[3 * i + 2];
    float h0 = fmaxf(fmaf(x0, sw[0], fmaf(x1, sw[3], fmaf(x2, sw[6], sb[0]))), 0.f);
    float h1 = fmaxf(fmaf(x0, sw[1], fmaf(x1, sw[4], fmaf(x2, sw[7], sb[1]))), 0.f);
    float h2 = fmaxf(fmaf(x0, sw[2], fmaf(x1, sw[5], fmaf(x2, sw[8], sb[2]))), 0.f);
    *(float4*)(g_HP + 4 * (size_t)i) = make_float4(h0, h1, h2, 0.f);
}

// ---------------- fused layer 1: gather-agg + update + project-2 ----------
__global__ void fused1_kernel(const float* __restrict__ x,
                              const float* __restrict__ lw,
                              const float* __restrict__ lb,
                              const float* __restrict__ rw,
                              const float* __restrict__ pw,
                              const float* __restrict__ pb) {
    __shared__ float s_lw[48], s_rw[48], s_lb[16], s_pw[256], s_pb[16];
    int t = threadIdx.x;
    if (t < 48) { s_lw[t] = lw[t]; s_rw[t] = rw[t]; }
    if (t < 16) { s_lb[t] = lb[t]; s_pb[t] = pb[t]; }
    s_pw[t] = pw[t];
    __syncthreads();
    int i = blockIdx.x * blockDim.x + t;
    if (i >= N_NODES) return;

    int beg = g_ROW[i], end = g_ROW[i + 1];
    float a0 = 0.f, a1 = 0.f, a2 = 0.f;
    int e = beg;
    for (; e + 1 < end; e += 2) {
        int s0 = g_CSR[e], s1 = g_CSR[e + 1];
        float4 v0 = *(const float4*)(g_HP + 4 * (size_t)s0);
        float4 v1 = *(const float4*)(g_HP + 4 * (size_t)s1);
        a0 += v0.x + v1.x; a1 += v0.y + v1.y; a2 += v0.z + v1.z;
    }
    if (e < end) {
        float4 v = *(const float4*)(g_HP + 4 * (size_t)g_CSR[e]);
        a0 += v.x; a1 += v.y; a2 += v.z;
    }

    float x0 = x[3 * i + 0], x1 = x[3 * i + 1], x2 = x[3 * i + 2];
    float acc[16];
    #pragma unroll
    for (int j = 0; j < 16; j++) {
        float v = s_lb[j];
        v = fmaf(a0, s_lw[j],      fmaf(x0, s_rw[j],      v));
        v = fmaf(a1, s_lw[16 + j], fmaf(x1, s_rw[16 + j], v));
        v = fmaf(a2, s_lw[32 + j], fmaf(x2, s_rw[32 + j], v));
        acc[j] = fmaxf(v, 0.f);
    }

    float4* xo = (float4*)(g_X1 + 16 * (size_t)i);
    xo[0] = make_float4(acc[0], acc[1], acc[2], acc[3]);
    xo[1] = make_float4(acc[4], acc[5], acc[6], acc[7]);
    xo[2] = make_float4(acc[8], acc[9], acc[10], acc[11]);
    xo[3] = make_float4(acc[12], acc[13], acc[14], acc[15]);

    float h[16];
    #pragma unroll
    for (int j = 0; j < 16; j++) h[j] = s_pb[j];
    #pragma unroll
    for (int k = 0; k < 16; k++)
        #pragma unroll
        for (int j = 0; j < 16; j++)
            h[j] = fmaf(acc[k], s_pw[k * 16 + j], h[j]);
    float4* ho = (float4*)(g_H + 16 * (size_t)i);
    ho[0] = make_float4(fmaxf(h[0], 0.f),  fmaxf(h[1], 0.f),  fmaxf(h[2], 0.f),  fmaxf(h[3], 0.f));
    ho[1] = make_float4(fmaxf(h[4], 0.f),  fmaxf(h[5], 0.f),  fmaxf(h[6], 0.f),  fmaxf(h[7], 0.f));
    ho[2] = make_float4(fmaxf(h[8], 0.f),  fmaxf(h[9], 0.f),  fmaxf(h[10], 0.f), fmaxf(h[11], 0.f));
    ho[3] = make_float4(fmaxf(h[12], 0.f), fmaxf(h[13], 0.f), fmaxf(h[14], 0.f), fmaxf(h[15], 0.f));
}

// ---------------- fused layer 2: gather-agg 16 + update + project-3 -------
__global__ void fused2_kernel(const float* __restrict__ lw,
                              const float* __restrict__ lb,
                              const float* __restrict__ rw,
                              const float* __restrict__ pw,
                              const float* __restrict__ pb) {
    __shared__ float s_lw[256], s_rw[256], s_lb[16], s_pw[256], s_pb[16];
    int t = threadIdx.x;
    s_lw[t] = lw[t]; s_rw[t] = rw[t]; s_pw[t] = pw[t];
    if (t < 16) { s_lb[t] = lb[t]; s_pb[t] = pb[t]; }
    __syncthreads();
    int i = blockIdx.x * blockDim.x + t;
    if (i >= N_NODES) return;

    int beg = g_ROW[i], end = g_ROW[i + 1];
    float4 A0 = make_float4(0, 0, 0, 0), A1 = A0, A2 = A0, A3 = A0;
    for (int e = beg; e < end; e++) {
        const float4* hv = (const float4*)(g_H + 16 * (size_t)g_CSR[e]);
        float4 v0 = hv[0], v1 = hv[1], v2 = hv[2], v3 = hv[3];
        A0.x += v0.x; A0.y += v0.y; A0.z += v0.z; A0.w += v0.w;
        A1.x += v1.x; A1.y += v1.y; A1.z += v1.z; A1.w += v1.w;
        A2.x += v2.x; A2.y += v2.y; A2.z += v2.z; A2.w += v2.w;
        A3.x += v3.x; A3.y += v3.y; A3.z += v3.z; A3.w += v3.w;
    }
    float a[16] = {A0.x, A0.y, A0.z, A0.w, A1.x, A1.y, A1.z, A1.w,
                   A2.x, A2.y, A2.z, A2.w, A3.x, A3.y, A3.z, A3.w};

    const float4* xv = (const float4*)(g_X1 + 16 * (size_t)i);
    float4 X0 = xv[0], X1v = xv[1], X2v = xv[2], X3 = xv[3];
    float xr[16] = {X0.x, X0.y, X0.z, X0.w, X1v.x, X1v.y, X1v.z, X1v.w,
                    X2v.x, X2v.y, X2v.z, X2v.w, X3.x, X3.y, X3.z, X3.w};

    float acc[16];
    #pragma unroll
    for (int j = 0; j < 16; j++) acc[j] = s_lb[j];
    #pragma unroll
    for (int k = 0; k < 16; k++)
        #pragma unroll
        for (int j = 0; j < 16; j++)
            acc[j] = fmaf(a[k], s_lw[k * 16 + j], fmaf(xr[k], s_rw[k * 16 + j], acc[j]));
    #pragma unroll
    for (int j = 0; j < 16; j++) acc[j] = fmaxf(acc[j], 0.f);

    float4* xo = (float4*)(g_X2 + 16 * (size_t)i);
    xo[0] = make_float4(acc[0], acc[1], acc[2], acc[3]);
    xo[1] = make_float4(acc[4], acc[5], acc[6], acc[7]);
    xo[2] = make_float4(acc[8], acc[9], acc[10], acc[11]);
    xo[3] = make_float4(acc[12], acc[13], acc[14], acc[15]);

    float h[16];
    #pragma unroll
    for (int j = 0; j < 16; j++) h[j] = s_pb[j];
    #pragma unroll
    for (int k = 0; k < 16; k++)
        #pragma unroll
        for (int j = 0; j < 16; j++)
            h[j] = fmaf(acc[k], s_pw[k * 16 + j], h[j]);
    float4* ho = (float4*)(g_H2 + 16 * (size_t)i);
    ho[0] = make_float4(fmaxf(h[0], 0.f),  fmaxf(h[1], 0.f),  fmaxf(h[2], 0.f),  fmaxf(h[3], 0.f));
    ho[1] = make_float4(fmaxf(h[4], 0.f),  fmaxf(h[5], 0.f),  fmaxf(h[6], 0.f),  fmaxf(h[7], 0.f));
    ho[2] = make_float4(fmaxf(h[8], 0.f),  fmaxf(h[9], 0.f),  fmaxf(h[10], 0.f), fmaxf(h[11], 0.f));
    ho[3] = make_float4(fmaxf(h[12], 0.f), fmaxf(h[13], 0.f), fmaxf(h[14], 0.f), fmaxf(h[15], 0.f));
}

// ---------------- fused layer 3: gather-agg + 16->1 + sigmoid -------------
__global__ void fused3_kernel(const float* __restrict__ lw,
                              const float* __restrict__ lb,
                              const float* __restrict__ rw,
                              float* __restrict__ out) {
    __shared__ float s_lw[16], s_rw[16], s_lb;
    int t = threadIdx.x;
    if (t < 16) { s_lw[t] = lw[t]; s_rw[t] = rw[t]; }
    if (t == 0) s_lb = lb[0];
    __syncthreads();
    int i = blockIdx.x * blockDim.x + t;
    if (i >= N_NODES) return;

    int beg = g_ROW[i], end = g_ROW[i + 1];
    float4 A0 = make_float4(0, 0, 0, 0), A1 = A0, A2 = A0, A3 = A0;
    for (int e = beg; e < end; e++) {
        const float4* hv = (const float4*)(g_H2 + 16 * (size_t)g_CSR[e]);
        float4 v0 = hv[0], v1 = hv[1], v2 = hv[2], v3 = hv[3];
        A0.x += v0.x; A0.y += v0.y; A0.z += v0.z; A0.w += v0.w;
        A1.x += v1.x; A1.y += v1.y; A1.z += v1.z; A1.w += v1.w;
        A2.x += v2.x; A2.y += v2.y; A2.z += v2.z; A2.w += v2.w;
        A3.x += v3.x; A3.y += v3.y; A3.z += v3.z; A3.w += v3.w;
    }

    const float4* xv = (const float4*)(g_X2 + 16 * (size_t)i);
    float4 X0 = xv[0], X1v = xv[1], X2v = xv[2], X3 = xv[3];

    float z = s_lb;
    z = fmaf(A0.x, s_lw[0],  z); z = fmaf(A0.y, s_lw[1],  z);
    z = fmaf(A0.z, s_lw[2],  z); z = fmaf(A0.w, s_lw[3],  z);
    z = fmaf(A1.x, s_lw[4],  z); z = fmaf(A1.y, s_lw[5],  z);
    z = fmaf(A1.z, s_lw[6],  z); z = fmaf(A1.w, s_lw[7],  z);
    z = fmaf(A2.x, s_lw[8],  z); z = fmaf(A2.y, s_lw[9],  z);
    z = fmaf(A2.z, s_lw[10], z); z = fmaf(A2.w, s_lw[11], z);
    z = fmaf(A3.x, s_lw[12], z); z = fmaf(A3.y, s_lw[13], z);
    z = fmaf(A3.z, s_lw[14], z); z = fmaf(A3.w, s_lw[15], z);
    z = fmaf(X0.x, s_rw[0],  z); z = fmaf(X0.y, s_rw[1],  z);
    z = fmaf(X0.z, s_rw[2],  z); z = fmaf(X0.w, s_rw[3],  z);
    z = fmaf(X1v.x, s_rw[4], z); z = fmaf(X1v.y, s_rw[5], z);
    z = fmaf(X1v.z, s_rw[6], z); z = fmaf(X1v.w, s_rw[7], z);
    z = fmaf(X2v.x, s_rw[8], z); z = fmaf(X2v.y, s_rw[9], z);
    z = fmaf(X2v.z, s_rw[10], z); z = fmaf(X2v.w, s_rw[11], z);
    z = fmaf(X3.x, s_rw[12], z); z = fmaf(X3.y, s_rw[13], z);
    z = fmaf(X3.z, s_rw[14], z); z = fmaf(X3.w, s_rw[15], z);

    out[i] = 1.f / (1.f + expf(-z));
}

// ---------------- launch ----------------
extern "C" void kernel_launch(void* const* d_in, const int* in_sizes, int n_in,
                              void* d_out, int out_size) {
    const float* x   = (const float*)d_in[0];
    const void*  ei  = d_in[1];
    const float* p1w = (const float*)d_in[2];
    const float* p1b = (const float*)d_in[3];
    const float* l1w = (const float*)d_in[4];
    const float* l1b = (const float*)d_in[5];
    const float* r1w = (const float*)d_in[6];
    const float* p2w = (const float*)d_in[7];
    const float* p2b = (const float*)d_in[8];
    const float* l2w = (const float*)d_in[9];
    const float* l2b = (const float*)d_in[10];
    const float* r2w = (const float*)d_in[11];
    const float* p3w = (const float*)d_in[12];
    const float* p3b = (const float*)d_in[13];
    const float* l3w = (const float*)d_in[14];
    const float* l3b = (const float*)d_in[15];
    const float* r3w = (const float*)d_in[16];
    float* out = (float*)d_out;

    void *degp = nullptr, *cntp = nullptr;
    cudaGetSymbolAddress(&degp, g_DEG);
    cudaGetSymbolAddress(&cntp, g_CNT);

    const int TB = 256;
    int gridE = (N_EDGES + TB - 1) / TB;
    int gridN = (N_NODES + TB - 1) / TB;

    // CSR build
    detect_kernel<<<1, 32>>>((const int*)ei);
    cudaMemsetAsync(degp, 0, (size_t)N_NODES * sizeof(int));
    conv_hist_kernel<<<gridE, TB>>>(ei);
    scan1_kernel<<<NSEG, SCAN_T>>>();
    scan2_kernel<<<1, SCAN_T>>>();
    scan3_kernel<<<NSEG, SCAN_T>>>();
    cudaMemsetAsync(cntp, 0, (size_t)N_NODES * sizeof(int));
    fill_kernel<<<gridE, TB>>>();

    // layers
    pre_kernel<<<gridN, TB>>>(x, p1w, p1b);
    fused1_kernel<<<gridN, TB>>>(x, l1w, l1b, r1w, p2w, p2b);
    fused2_kernel<<<gridN, TB>>>(l2w, l2b, r2w, p3w, p3b);
    fused3_kernel<<<gridN, TB>>>(l3w, l3b, r3w, out);
}

// round 6
// speedup vs baseline: 3.3324x; 2.1006x over previous
#include <cuda_runtime.h>
#include <math.h>

#define N_NODES 500000
#define N_EDGES 5000000

#define SCAN_T 256
#define SCAN_I 8
#define SEG (SCAN_T * SCAN_I)                 // 2048
#define NSEG ((N_NODES + SEG - 1) / SEG)      // 245

// ---------------- scratch (device globals: allocation-free) ----------------
__device__ float g_HP [N_NODES * 4];    // layer-1 projected features (padded to 4)
__device__ float g_H  [N_NODES * 16];   // layer-2 messages
__device__ float g_H2 [N_NODES * 16];   // layer-3 messages
__device__ float g_X1 [N_NODES * 16];   // layer-1 output
__device__ float g_X2 [N_NODES * 16];   // layer-2 output
__device__ int   g_CSR[N_EDGES];        // src indices sorted by dst
__device__ int   g_ROW[N_NODES + 1];    // CSR row offsets
__device__ int   g_DEG[N_NODES];
__device__ int   g_CNT[N_NODES];        // running fill cursor (init = ROW)
__device__ int   g_BSUM[NSEG];
__device__ int   g_BOFF[NSEG];
__device__ int   g_IS64;

// ---------------- index dtype detection ----------------
__global__ void detect_kernel(const int* __restrict__ p) {
    if (threadIdx.x == 0) {
        int is64 = 1;
        #pragma unroll 1
        for (int i = 0; i < 64; i++)
            if (p[2 * i + 1] != 0) { is64 = 0; break; }
        g_IS64 = is64;
    }
}

// histogram of dst degrees (reads only the dst half of edge_index)
__global__ void hist_kernel(const void* __restrict__ ei) {
    int e = blockIdx.x * blockDim.x + threadIdx.x;
    if (e >= N_EDGES) return;
    int d;
    if (g_IS64) d = (int)((const long long*)ei)[(size_t)N_EDGES + e];
    else        d = ((const int*)ei)[N_EDGES + e];
    atomicAdd(&g_DEG[d], 1);
}

// ---------------- exclusive scan of g_DEG -> g_ROW (3 passes) --------------
__global__ void scan1_kernel() {          // per-segment reduce
    __shared__ int sm[SCAN_T];
    int t = threadIdx.x;
    int base = blockIdx.x * SEG + t * SCAN_I;
    int sum = 0;
    #pragma unroll
    for (int k = 0; k < SCAN_I; k++) {
        int i = base + k;
        if (i < N_NODES) sum += g_DEG[i];
    }
    sm[t] = sum;
    __syncthreads();
    for (int off = SCAN_T / 2; off > 0; off >>= 1) {
        if (t < off) sm[t] += sm[t + off];
        __syncthreads();
    }
    if (t == 0) g_BSUM[blockIdx.x] = sm[0];
}

__global__ void scan2_kernel() {          // single-block scan of segment sums
    __shared__ int sm[SCAN_T];
    int t = threadIdx.x;
    int v = (t < NSEG) ? g_BSUM[t] : 0;
    sm[t] = v;
    __syncthreads();
    for (int off = 1; off < SCAN_T; off <<= 1) {
        int x = (t >= off) ? sm[t - off] : 0;
        __syncthreads();
        sm[t] += x;
        __syncthreads();
    }
    if (t < NSEG) g_BOFF[t] = sm[t] - v;   // exclusive
    if (t == 0) g_ROW[N_NODES] = N_EDGES;
}

__global__ void scan3_kernel() {          // write exclusive prefix into g_ROW
    __shared__ int sm[SCAN_T];
    int t = threadIdx.x;
    int base = blockIdx.x * SEG + t * SCAN_I;
    int deg[SCAN_I];
    int tsum = 0;
    #pragma unroll
    for (int k = 0; k < SCAN_I; k++) {
        int i = base + k;
        deg[k] = (i < N_NODES) ? g_DEG[i] : 0;
        tsum += deg[k];
    }
    sm[t] = tsum;
    __syncthreads();
    for (int off = 1; off < SCAN_T; off <<= 1) {
        int x = (t >= off) ? sm[t - off] : 0;
        __syncthreads();
        sm[t] += x;
        __syncthreads();
    }
    int run = g_BOFF[blockIdx.x] + sm[t] - tsum;
    #pragma unroll
    for (int k = 0; k < SCAN_I; k++) {
        int i = base + k;
        if (i < N_NODES) g_ROW[i] = run;
        run += deg[k];
    }
}

// fill CSR directly from edge_index; g_CNT was pre-initialized to g_ROW
__global__ void fill_kernel(const void* __restrict__ ei) {
    int e = blockIdx.x * blockDim.x + threadIdx.x;
    if (e >= N_EDGES) return;
    int s, d;
    if (g_IS64) {
        const long long* p = (const long long*)ei;
        s = (int)p[e];
        d = (int)p[(size_t)N_EDGES + e];
    } else {
        const int* p = (const int*)ei;
        s = p[e];
        d = p[N_EDGES + e];
    }
    int pos = atomicAdd(&g_CNT[d], 1);
    g_CSR[pos] = s;
}

// ---------------- layer-1 projection (din=3), padded to stride 4 ----------
__global__ void pre_kernel(const float* __restrict__ x,
                           const float* __restrict__ pw,
                           const float* __restrict__ pb) {
    __shared__ float sw[9], sb[3];
    int t = threadIdx.x;
    if (t < 9) sw[t] = pw[t];
    if (t < 3) sb[t] = pb[t];
    __syncthreads();
    int i = blockIdx.x * blockDim.x + t;
    if (i >= N_NODES) return;
    float x0 = x[3 * i + 0], x1 = x[3 * i + 1], x2 = x[3 * i + 2];
    float h0 = fmaxf(fmaf(x0, sw[0], fmaf(x1, sw[3], fmaf(x2, sw[6], sb[0]))), 0.f);
    float h1 = fmaxf(fmaf(x0, sw[1], fmaf(x1, sw[4], fmaf(x2, sw[7], sb[1]))), 0.f);
    float h2 = fmaxf(fmaf(x0, sw[2], fmaf(x1, sw[5], fmaf(x2, sw[8], sb[2]))), 0.f);
    *(float4*)(g_HP + 4 * (size_t)i) = make_float4(h0, h1, h2, 0.f);
}

// ---------------- fused layer 1: gather-agg + update + project-2 ----------
// thread-per-node (rows are only 16B), unrolled x4 for MLP
__global__ void fused1_kernel(const float* __restrict__ x,
                              const float* __restrict__ lw,
                              const float* __restrict__ lb,
                              const float* __restrict__ rw,
                              const float* __restrict__ pw,
                              const float* __restrict__ pb) {
    __shared__ float s_lw[48], s_rw[48], s_lb[16], s_pw[256], s_pb[16];
    int t = threadIdx.x;
    if (t < 48) { s_lw[t] = lw[t]; s_rw[t] = rw[t]; }
    if (t < 16) { s_lb[t] = lb[t]; s_pb[t] = pb[t]; }
    s_pw[t] = pw[t];
    __syncthreads();
    int i = blockIdx.x * blockDim.x + t;
    if (i >= N_NODES) return;

    int beg = g_ROW[i], end = g_ROW[i + 1];
    float a0 = 0.f, a1 = 0.f, a2 = 0.f;
    float b0 = 0.f, b1 = 0.f, b2 = 0.f;
    int e = beg;
    for (; e + 3 < end; e += 4) {
        int s0 = __ldg(&g_CSR[e]),     s1 = __ldg(&g_CSR[e + 1]);
        int s2 = __ldg(&g_CSR[e + 2]), s3 = __ldg(&g_CSR[e + 3]);
        float4 v0 = *(const float4*)(g_HP + 4 * (size_t)s0);
        float4 v1 = *(const float4*)(g_HP + 4 * (size_t)s1);
        float4 v2 = *(const float4*)(g_HP + 4 * (size_t)s2);
        float4 v3 = *(const float4*)(g_HP + 4 * (size_t)s3);
        a0 += v0.x + v1.x; a1 += v0.y + v1.y; a2 += v0.z + v1.z;
        b0 += v2.x + v3.x; b1 += v2.y + v3.y; b2 += v2.z + v3.z;
    }
    for (; e < end; e++) {
        float4 v = *(const float4*)(g_HP + 4 * (size_t)__ldg(&g_CSR[e]));
        a0 += v.x; a1 += v.y; a2 += v.z;
    }
    a0 += b0; a1 += b1; a2 += b2;

    float x0 = x[3 * i + 0], x1 = x[3 * i + 1], x2 = x[3 * i + 2];
    float acc[16];
    #pragma unroll
    for (int j = 0; j < 16; j++) {
        float v = s_lb[j];
        v = fmaf(a0, s_lw[j],      fmaf(x0, s_rw[j],      v));
        v = fmaf(a1, s_lw[16 + j], fmaf(x1, s_rw[16 + j], v));
        v = fmaf(a2, s_lw[32 + j], fmaf(x2, s_rw[32 + j], v));
        acc[j] = fmaxf(v, 0.f);
    }

    float4* xo = (float4*)(g_X1 + 16 * (size_t)i);
    xo[0] = make_float4(acc[0], acc[1], acc[2], acc[3]);
    xo[1] = make_float4(acc[4], acc[5], acc[6], acc[7]);
    xo[2] = make_float4(acc[8], acc[9], acc[10], acc[11]);
    xo[3] = make_float4(acc[12], acc[13], acc[14], acc[15]);

    float h[16];
    #pragma unroll
    for (int j = 0; j < 16; j++) h[j] = s_pb[j];
    #pragma unroll
    for (int k = 0; k < 16; k++)
        #pragma unroll
        for (int j = 0; j < 16; j++)
            h[j] = fmaf(acc[k], s_pw[k * 16 + j], h[j]);
    float4* ho = (float4*)(g_H + 16 * (size_t)i);
    ho[0] = make_float4(fmaxf(h[0], 0.f),  fmaxf(h[1], 0.f),  fmaxf(h[2], 0.f),  fmaxf(h[3], 0.f));
    ho[1] = make_float4(fmaxf(h[4], 0.f),  fmaxf(h[5], 0.f),  fmaxf(h[6], 0.f),  fmaxf(h[7], 0.f));
    ho[2] = make_float4(fmaxf(h[8], 0.f),  fmaxf(h[9], 0.f),  fmaxf(h[10], 0.f), fmaxf(h[11], 0.f));
    ho[3] = make_float4(fmaxf(h[12], 0.f), fmaxf(h[13], 0.f), fmaxf(h[14], 0.f), fmaxf(h[15], 0.f));
}

// ---------------- fused layer 2: 4 lanes per node -------------------------
// lane l4 owns feature chunk [4*l4, 4*l4+4). Gather loads are coalesced 64B
// per group; epilogue matmul uses warp shuffles to assemble full vectors.
__global__ void fused2_kernel(const float* __restrict__ lw,
                              const float* __restrict__ lb,
                              const float* __restrict__ rw,
                              const float* __restrict__ pw,
                              const float* __restrict__ pb) {
    __shared__ float s_lw[256], s_rw[256], s_lb[16], s_pw[256], s_pb[16];
    int t = threadIdx.x;
    s_lw[t] = lw[t]; s_rw[t] = rw[t]; s_pw[t] = pw[t];
    if (t < 16) { s_lb[t] = lb[t]; s_pb[t] = pb[t]; }
    __syncthreads();

    int g  = t >> 2;          // node group within block (0..63)
    int l4 = t & 3;           // lane within group
    int i  = blockIdx.x * 64 + g;
    if (i >= N_NODES) return; // N_NODES%8==0 -> whole warps exit only

    int lane = t & 31;
    int base = lane & ~3;

    int beg = g_ROW[i], end = g_ROW[i + 1];
    float4 A = make_float4(0.f, 0.f, 0.f, 0.f);
    float4 B = make_float4(0.f, 0.f, 0.f, 0.f);
    int e = beg;
    for (; e + 1 < end; e += 2) {
        int s0 = __ldg(&g_CSR[e]);
        int s1 = __ldg(&g_CSR[e + 1]);
        float4 v0 = *(const float4*)(g_H + 16 * (size_t)s0 + 4 * l4);
        float4 v1 = *(const float4*)(g_H + 16 * (size_t)s1 + 4 * l4);
        A.x += v0.x; A.y += v0.y; A.z += v0.z; A.w += v0.w;
        B.x += v1.x; B.y += v1.y; B.z += v1.z; B.w += v1.w;
    }
    if (e < end) {
        float4 v = *(const float4*)(g_H + 16 * (size_t)__ldg(&g_CSR[e]) + 4 * l4);
        A.x += v.x; A.y += v.y; A.z += v.z; A.w += v.w;
    }
    A.x += B.x; A.y += B.y; A.z += B.z; A.w += B.w;

    float4 X = *(const float4*)(g_X1 + 16 * (size_t)i + 4 * l4);

    // assemble full 16-vectors via shuffles
    float a[16], xr[16];
    #pragma unroll
    for (int r = 0; r < 4; r++) {
        a[4 * r + 0]  = __shfl_sync(0xffffffffu, A.x, base + r);
        a[4 * r + 1]  = __shfl_sync(0xffffffffu, A.y, base + r);
        a[4 * r + 2]  = __shfl_sync(0xffffffffu, A.z, base + r);
        a[4 * r + 3]  = __shfl_sync(0xffffffffu, A.w, base + r);
        xr[4 * r + 0] = __shfl_sync(0xffffffffu, X.x, base + r);
        xr[4 * r + 1] = __shfl_sync(0xffffffffu, X.y, base + r);
        xr[4 * r + 2] = __shfl_sync(0xffffffffu, X.z, base + r);
        xr[4 * r + 3] = __shfl_sync(0xffffffffu, X.w, base + r);
    }

    // each lane computes 4 outputs j in [4*l4, 4*l4+4)
    int jb = 4 * l4;
    float acc4[4];
    #pragma unroll
    for (int j0 = 0; j0 < 4; j0++) acc4[j0] = s_lb[jb + j0];
    #pragma unroll
    for (int k = 0; k < 16; k++)
        #pragma unroll
        for (int j0 = 0; j0 < 4; j0++)
            acc4[j0] = fmaf(a[k], s_lw[k * 16 + jb + j0],
                       fmaf(xr[k], s_rw[k * 16 + jb + j0], acc4[j0]));
    #pragma unroll
    for (int j0 = 0; j0 < 4; j0++) acc4[j0] = fmaxf(acc4[j0], 0.f);

    *(float4*)(g_X2 + 16 * (size_t)i + jb) =
        make_float4(acc4[0], acc4[1], acc4[2], acc4[3]);

    // fused project-3: need full acc vector -> shuffle again
    float ac[16];
    #pragma unroll
    for (int r = 0; r < 4; r++) {
        ac[4 * r + 0] = __shfl_sync(0xffffffffu, acc4[0], base + r);
        ac[4 * r + 1] = __shfl_sync(0xffffffffu, acc4[1], base + r);
        ac[4 * r + 2] = __shfl_sync(0xffffffffu, acc4[2], base + r);
        ac[4 * r + 3] = __shfl_sync(0xffffffffu, acc4[3], base + r);
    }
    float h4[4];
    #pragma unroll
    for (int j0 = 0; j0 < 4; j0++) h4[j0] = s_pb[jb + j0];
    #pragma unroll
    for (int k = 0; k < 16; k++)
        #pragma unroll
        for (int j0 = 0; j0 < 4; j0++)
            h4[j0] = fmaf(ac[k], s_pw[k * 16 + jb + j0], h4[j0]);
    *(float4*)(g_H2 + 16 * (size_t)i + jb) =
        make_float4(fmaxf(h4[0], 0.f), fmaxf(h4[1], 0.f),
                    fmaxf(h4[2], 0.f), fmaxf(h4[3], 0.f));
}

// ---------------- fused layer 3: 4 lanes per node, 16->1 + sigmoid --------
__global__ void fused3_kernel(const float* __restrict__ lw,
                              const float* __restrict__ lb,
                              const float* __restrict__ rw,
                              float* __restrict__ out) {
    __shared__ float s_lw[16], s_rw[16], s_lb;
    int t = threadIdx.x;
    if (t < 16) { s_lw[t] = lw[t]; s_rw[t] = rw[t]; }
    if (t == 0) s_lb = lb[0];
    __syncthreads();

    int g  = t >> 2;
    int l4 = t & 3;
    int i  = blockIdx.x * 64 + g;
    if (i >= N_NODES) return;

    int beg = g_ROW[i], end = g_ROW[i + 1];
    float4 A = make_float4(0.f, 0.f, 0.f, 0.f);
    float4 B = make_float4(0.f, 0.f, 0.f, 0.f);
    int e = beg;
    for (; e + 1 < end; e += 2) {
        int s0 = __ldg(&g_CSR[e]);
        int s1 = __ldg(&g_CSR[e + 1]);
        float4 v0 = *(const float4*)(g_H2 + 16 * (size_t)s0 + 4 * l4);
        float4 v1 = *(const float4*)(g_H2 + 16 * (size_t)s1 + 4 * l4);
        A.x += v0.x; A.y += v0.y; A.z += v0.z; A.w += v0.w;
        B.x += v1.x; B.y += v1.y; B.z += v1.z; B.w += v1.w;
    }
    if (e < end) {
        float4 v = *(const float4*)(g_H2 + 16 * (size_t)__ldg(&g_CSR[e]) + 4 * l4);
        A.x += v.x; A.y += v.y; A.z += v.z; A.w += v.w;
    }
    A.x += B.x; A.y += B.y; A.z += B.z; A.w += B.w;

    float4 X = *(const float4*)(g_X2 + 16 * (size_t)i + 4 * l4);

    int jb = 4 * l4;
    float z = fmaf(A.x, s_lw[jb + 0], 0.f);
    z = fmaf(A.y, s_lw[jb + 1], z);
    z = fmaf(A.z, s_lw[jb + 2], z);
    z = fmaf(A.w, s_lw[jb + 3], z);
    z = fmaf(X.x, s_rw[jb + 0], z);
    z = fmaf(X.y, s_rw[jb + 1], z);
    z = fmaf(X.z, s_rw[jb + 2], z);
    z = fmaf(X.w, s_rw[jb + 3], z);

    z += __shfl_xor_sync(0xffffffffu, z, 1);
    z += __shfl_xor_sync(0xffffffffu, z, 2);

    if (l4 == 0) out[i] = 1.f / (1.f + expf(-(z + s_lb)));
}

// ---------------- launch ----------------
extern "C" void kernel_launch(void* const* d_in, const int* in_sizes, int n_in,
                              void* d_out, int out_size) {
    const float* x   = (const float*)d_in[0];
    const void*  ei  = d_in[1];
    const float* p1w = (const float*)d_in[2];
    const float* p1b = (const float*)d_in[3];
    const float* l1w = (const float*)d_in[4];
    const float* l1b = (const float*)d_in[5];
    const float* r1w = (const float*)d_in[6];
    const float* p2w = (const float*)d_in[7];
    const float* p2b = (const float*)d_in[8];
    const float* l2w = (const float*)d_in[9];
    const float* l2b = (const float*)d_in[10];
    const float* r2w = (const float*)d_in[11];
    const float* p3w = (const float*)d_in[12];
    const float* p3b = (const float*)d_in[13];
    const float* l3w = (const float*)d_in[14];
    const float* l3b = (const float*)d_in[15];
    const float* r3w = (const float*)d_in[16];
    float* out = (float*)d_out;

    void *degp = nullptr, *cntp = nullptr, *rowp = nullptr;
    cudaGetSymbolAddress(&degp, g_DEG);
    cudaGetSymbolAddress(&cntp, g_CNT);
    cudaGetSymbolAddress(&rowp, g_ROW);

    const int TB = 256;
    int gridE = (N_EDGES + TB - 1) / TB;
    int gridN = (N_NODES + TB - 1) / TB;
    int gridN4 = (N_NODES * 4 + TB - 1) / TB;   // 4 lanes per node

    // CSR build
    detect_kernel<<<1, 32>>>((const int*)ei);
    cudaMemsetAsync(degp, 0, (size_t)N_NODES * sizeof(int));
    hist_kernel<<<gridE, TB>>>(ei);
    scan1_kernel<<<NSEG, SCAN_T>>>();
    scan2_kernel<<<1, SCAN_T>>>();
    scan3_kernel<<<NSEG, SCAN_T>>>();
    cudaMemcpyAsync(cntp, rowp, (size_t)N_NODES * sizeof(int),
                    cudaMemcpyDeviceToDevice);
    fill_kernel<<<gridE, TB>>>(ei);

    // layers
    pre_kernel<<<gridN, TB>>>(x, p1w, p1b);
    fused1_kernel<<<gridN, TB>>>(x, l1w, l1b, r1w, p2w, p2b);
    fused2_kernel<<<gridN4, TB>>>(l2w, l2b, r2w, p3w, p3b);
    fused3_kernel<<<gridN4, TB>>>(l3w, l3b, r3w, out);
}

// round 8
// speedup vs baseline: 3.5354x; 1.0609x over previous
#include <cuda_runtime.h>
#include <math.h>

#define N_NODES 500000
#define N_EDGES 5000000

#define SCAN_T 256
#define SCAN_I 8
#define SEG (SCAN_T * SCAN_I)                 // 2048
#define NSEG ((N_NODES + SEG - 1) / SEG)      // 245

// ---------------- scratch (device globals: allocation-free) ----------------
__device__ float g_HP [N_NODES * 4];    // layer-1 messages (fp32, padded to 4)
__device__ float g_H  [N_NODES * 16];   // layer-2 messages (fp32)
__device__ float g_M3 [N_NODES];        // layer-3 scalar messages: h3 . l3_w
__device__ float g_X1 [N_NODES * 16];   // layer-1 output
__device__ float g_X2 [N_NODES * 16];   // layer-2 output
__device__ int   g_CSR[N_EDGES];        // src indices sorted by dst
__device__ int   g_ROW[N_NODES + 1];    // CSR row offsets
__device__ int   g_DEG[N_NODES];
__device__ int   g_CNT[N_NODES];        // running fill cursor (init = ROW)
__device__ int   g_BSUM[NSEG];
__device__ int   g_BOFF[NSEG];
__device__ int   g_IS64;

// ---------------- index dtype detection ----------------
__global__ void detect_kernel(const int* __restrict__ p) {
    if (threadIdx.x == 0) {
        int is64 = 1;
        #pragma unroll 1
        for (int i = 0; i < 64; i++)
            if (p[2 * i + 1] != 0) { is64 = 0; break; }
        g_IS64 = is64;
    }
}

// histogram of dst degrees (reads only the dst half of edge_index)
__global__ void hist_kernel(const void* __restrict__ ei) {
    int e = blockIdx.x * blockDim.x + threadIdx.x;
    if (e >= N_EDGES) return;
    int d;
    if (g_IS64) d = (int)((const long long*)ei)[(size_t)N_EDGES + e];
    else        d = ((const int*)ei)[N_EDGES + e];
    atomicAdd(&g_DEG[d], 1);
}

// ---------------- exclusive scan of g_DEG -> g_ROW (3 passes) --------------
__global__ void scan1_kernel() {          // per-segment reduce
    __shared__ int sm[SCAN_T];
    int t = threadIdx.x;
    int base = blockIdx.x * SEG + t * SCAN_I;
    int sum = 0;
    #pragma unroll
    for (int k = 0; k < SCAN_I; k++) {
        int i = base + k;
        if (i < N_NODES) sum += g_DEG[i];
    }
    sm[t] = sum;
    __syncthreads();
    for (int off = SCAN_T / 2; off > 0; off >>= 1) {
        if (t < off) sm[t] += sm[t + off];
        __syncthreads();
    }
    if (t == 0) g_BSUM[blockIdx.x] = sm[0];
}

__global__ void scan2_kernel() {          // single-block scan of segment sums
    __shared__ int sm[SCAN_T];
    int t = threadIdx.x;
    int v = (t < NSEG) ? g_BSUM[t] : 0;
    sm[t] = v;
    __syncthreads();
    for (int off = 1; off < SCAN_T; off <<= 1) {
        int x = (t >= off) ? sm[t - off] : 0;
        __syncthreads();
        sm[t] += x;
        __syncthreads();
    }
    if (t < NSEG) g_BOFF[t] = sm[t] - v;   // exclusive
    if (t == 0) g_ROW[N_NODES] = N_EDGES;
}

__global__ void scan3_kernel() {          // write exclusive prefix into g_ROW
    __shared__ int sm[SCAN_T];
    int t = threadIdx.x;
    int base = blockIdx.x * SEG + t * SCAN_I;
    int deg[SCAN_I];
    int tsum = 0;
    #pragma unroll
    for (int k = 0; k < SCAN_I; k++) {
        int i = base + k;
        deg[k] = (i < N_NODES) ? g_DEG[i] : 0;
        tsum += deg[k];
    }
    sm[t] = tsum;
    __syncthreads();
    for (int off = 1; off < SCAN_T; off <<= 1) {
        int x = (t >= off) ? sm[t - off] : 0;
        __syncthreads();
        sm[t] += x;
        __syncthreads();
    }
    int run = g_BOFF[blockIdx.x] + sm[t] - tsum;
    #pragma unroll
    for (int k = 0; k < SCAN_I; k++) {
        int i = base + k;
        if (i < N_NODES) g_ROW[i] = run;
        run += deg[k];
    }
}

// fill CSR directly from edge_index; g_CNT was pre-initialized to g_ROW
__global__ void fill_kernel(const void* __restrict__ ei) {
    int e = blockIdx.x * blockDim.x + threadIdx.x;
    if (e >= N_EDGES) return;
    int s, d;
    if (g_IS64) {
        const long long* p = (const long long*)ei;
        s = (int)p[e];
        d = (int)p[(size_t)N_EDGES + e];
    } else {
        const int* p = (const int*)ei;
        s = p[e];
        d = p[N_EDGES + e];
    }
    int pos = atomicAdd(&g_CNT[d], 1);
    g_CSR[pos] = s;
}

// ---------------- layer-1 projection (din=3), padded to stride 4 ----------
__global__ void pre_kernel(const float* __restrict__ x,
                           const float* __restrict__ pw,
                           const float* __restrict__ pb) {
    __shared__ float sw[9], sb[3];
    int t = threadIdx.x;
    if (t < 9) sw[t] = pw[t];
    if (t < 3) sb[t] = pb[t];
    __syncthreads();
    int i = blockIdx.x * blockDim.x + t;
    if (i >= N_NODES) return;
    float x0 = x[3 * i + 0], x1 = x[3 * i + 1], x2 = x[3 * i + 2];
    float h0 = fmaxf(fmaf(x0, sw[0], fmaf(x1, sw[3], fmaf(x2, sw[6], sb[0]))), 0.f);
    float h1 = fmaxf(fmaf(x0, sw[1], fmaf(x1, sw[4], fmaf(x2, sw[7], sb[1]))), 0.f);
    float h2 = fmaxf(fmaf(x0, sw[2], fmaf(x1, sw[5], fmaf(x2, sw[8], sb[2]))), 0.f);
    *(float4*)(g_HP + 4 * (size_t)i) = make_float4(h0, h1, h2, 0.f);
}

// ---------------- fused layer 1: gather-agg + update + project-2 ----------
// thread-per-node (rows are only 16B), unrolled x4 for MLP
__global__ void fused1_kernel(const float* __restrict__ x,
                              const float* __restrict__ lw,
                              const float* __restrict__ lb,
                              const float* __restrict__ rw,
                              const float* __restrict__ pw,
                              const float* __restrict__ pb) {
    __shared__ float s_lw[48], s_rw[48], s_lb[16], s_pw[256], s_pb[16];
    int t = threadIdx.x;
    if (t < 48) { s_lw[t] = lw[t]; s_rw[t] = rw[t]; }
    if (t < 16) { s_lb[t] = lb[t]; s_pb[t] = pb[t]; }
    s_pw[t] = pw[t];
    __syncthreads();
    int i = blockIdx.x * blockDim.x + t;
    if (i >= N_NODES) return;

    int beg = g_ROW[i], end = g_ROW[i + 1];
    float a0 = 0.f, a1 = 0.f, a2 = 0.f;
    float b0 = 0.f, b1 = 0.f, b2 = 0.f;
    int e = beg;
    for (; e + 3 < end; e += 4) {
        int s0 = __ldg(&g_CSR[e]),     s1 = __ldg(&g_CSR[e + 1]);
        int s2 = __ldg(&g_CSR[e + 2]), s3 = __ldg(&g_CSR[e + 3]);
        float4 v0 = *(const float4*)(g_HP + 4 * (size_t)s0);
        float4 v1 = *(const float4*)(g_HP + 4 * (size_t)s1);
        float4 v2 = *(const float4*)(g_HP + 4 * (size_t)s2);
        float4 v3 = *(const float4*)(g_HP + 4 * (size_t)s3);
        a0 += v0.x + v1.x; a1 += v0.y + v1.y; a2 += v0.z + v1.z;
        b0 += v2.x + v3.x; b1 += v2.y + v3.y; b2 += v2.z + v3.z;
    }
    for (; e < end; e++) {
        float4 v = *(const float4*)(g_HP + 4 * (size_t)__ldg(&g_CSR[e]));
        a0 += v.x; a1 += v.y; a2 += v.z;
    }
    a0 += b0; a1 += b1; a2 += b2;

    float x0 = x[3 * i + 0], x1 = x[3 * i + 1], x2 = x[3 * i + 2];
    float acc[16];
    #pragma unroll
    for (int j = 0; j < 16; j++) {
        float v = s_lb[j];
        v = fmaf(a0, s_lw[j],      fmaf(x0, s_rw[j],      v));
        v = fmaf(a1, s_lw[16 + j], fmaf(x1, s_rw[16 + j], v));
        v = fmaf(a2, s_lw[32 + j], fmaf(x2, s_rw[32 + j], v));
        acc[j] = fmaxf(v, 0.f);
    }

    float4* xo = (float4*)(g_X1 + 16 * (size_t)i);
    xo[0] = make_float4(acc[0], acc[1], acc[2], acc[3]);
    xo[1] = make_float4(acc[4], acc[5], acc[6], acc[7]);
    xo[2] = make_float4(acc[8], acc[9], acc[10], acc[11]);
    xo[3] = make_float4(acc[12], acc[13], acc[14], acc[15]);

    float h[16];
    #pragma unroll
    for (int j = 0; j < 16; j++) h[j] = s_pb[j];
    #pragma unroll
    for (int k = 0; k < 16; k++)
        #pragma unroll
        for (int j = 0; j < 16; j++)
            h[j] = fmaf(acc[k], s_pw[k * 16 + j], h[j]);
    float4* ho = (float4*)(g_H + 16 * (size_t)i);
    ho[0] = make_float4(fmaxf(h[0], 0.f),  fmaxf(h[1], 0.f),  fmaxf(h[2], 0.f),  fmaxf(h[3], 0.f));
    ho[1] = make_float4(fmaxf(h[4], 0.f),  fmaxf(h[5], 0.f),  fmaxf(h[6], 0.f),  fmaxf(h[7], 0.f));
    ho[2] = make_float4(fmaxf(h[8], 0.f),  fmaxf(h[9], 0.f),  fmaxf(h[10], 0.f), fmaxf(h[11], 0.f));
    ho[3] = make_float4(fmaxf(h[12], 0.f), fmaxf(h[13], 0.f), fmaxf(h[14], 0.f), fmaxf(h[15], 0.f));
}

// ---------------- fused layer 2: 4 lanes per node -------------------------
// lane l4 owns feature chunk [4*l4, 4*l4+4). Gather loads are coalesced 64B
// per group. Epilogue computes x2 (fp32) AND the layer-3 scalar message
// m3[i] = relu(x2 @ p3_w + p3_b) . l3_w  (layer 3 has dout=1, so the whole
// 16-wide message collapses to one float by linearity of the aggregation).
__global__ void fused2_kernel(const float* __restrict__ lw,
                              const float* __restrict__ lb,
                              const float* __restrict__ rw,
                              const float* __restrict__ pw,
                              const float* __restrict__ pb,
                              const float* __restrict__ l3w) {
    __shared__ float s_lw[256], s_rw[256], s_lb[16], s_pw[256], s_pb[16], s_l3w[16];
    int t = threadIdx.x;
    s_lw[t] = lw[t]; s_rw[t] = rw[t]; s_pw[t] = pw[t];
    if (t < 16) { s_lb[t] = lb[t]; s_pb[t] = pb[t]; s_l3w[t] = l3w[t]; }
    __syncthreads();

    int g  = t >> 2;          // node group within block (0..63)
    int l4 = t & 3;           // lane within group
    int i  = blockIdx.x * 64 + g;
    if (i >= N_NODES) return; // N_NODES%8==0 -> whole warps exit only

    int lane = t & 31;
    int base = lane & ~3;

    int beg = g_ROW[i], end = g_ROW[i + 1];
    float4 A = make_float4(0.f, 0.f, 0.f, 0.f);
    float4 B = make_float4(0.f, 0.f, 0.f, 0.f);
    int e = beg;
    for (; e + 1 < end; e += 2) {
        int s0 = __ldg(&g_CSR[e]);
        int s1 = __ldg(&g_CSR[e + 1]);
        float4 v0 = *(const float4*)(g_H + 16 * (size_t)s0 + 4 * l4);
        float4 v1 = *(const float4*)(g_H + 16 * (size_t)s1 + 4 * l4);
        A.x += v0.x; A.y += v0.y; A.z += v0.z; A.w += v0.w;
        B.x += v1.x; B.y += v1.y; B.z += v1.z; B.w += v1.w;
    }
    if (e < end) {
        float4 v = *(const float4*)(g_H + 16 * (size_t)__ldg(&g_CSR[e]) + 4 * l4);
        A.x += v.x; A.y += v.y; A.z += v.z; A.w += v.w;
    }
    A.x += B.x; A.y += B.y; A.z += B.z; A.w += B.w;

    float4 X = *(const float4*)(g_X1 + 16 * (size_t)i + 4 * l4);

    // assemble full 16-vectors via shuffles
    float a[16], xr[16];
    #pragma unroll
    for (int r = 0; r < 4; r++) {
        a[4 * r + 0]  = __shfl_sync(0xffffffffu, A.x, base + r);
        a[4 * r + 1]  = __shfl_sync(0xffffffffu, A.y, base + r);
        a[4 * r + 2]  = __shfl_sync(0xffffffffu, A.z, base + r);
        a[4 * r + 3]  = __shfl_sync(0xffffffffu, A.w, base + r);
        xr[4 * r + 0] = __shfl_sync(0xffffffffu, X.x, base + r);
        xr[4 * r + 1] = __shfl_sync(0xffffffffu, X.y, base + r);
        xr[4 * r + 2] = __shfl_sync(0xffffffffu, X.z, base + r);
        xr[4 * r + 3] = __shfl_sync(0xffffffffu, X.w, base + r);
    }

    // each lane computes 4 outputs j in [4*l4, 4*l4+4)
    int jb = 4 * l4;
    float acc4[4];
    #pragma unroll
    for (int j0 = 0; j0 < 4; j0++) acc4[j0] = s_lb[jb + j0];
    #pragma unroll
    for (int k = 0; k < 16; k++)
        #pragma unroll
        for (int j0 = 0; j0 < 4; j0++)
            acc4[j0] = fmaf(a[k], s_lw[k * 16 + jb + j0],
                       fmaf(xr[k], s_rw[k * 16 + jb + j0], acc4[j0]));
    #pragma unroll
    for (int j0 = 0; j0 < 4; j0++) acc4[j0] = fmaxf(acc4[j0], 0.f);

    *(float4*)(g_X2 + 16 * (size_t)i + jb) =
        make_float4(acc4[0], acc4[1], acc4[2], acc4[3]);

    // fused project-3: need full acc vector -> shuffle again
    float ac[16];
    #pragma unroll
    for (int r = 0; r < 4; r++) {
        ac[4 * r + 0] = __shfl_sync(0xffffffffu, acc4[0], base + r);
        ac[4 * r + 1] = __shfl_sync(0xffffffffu, acc4[1], base + r);
        ac[4 * r + 2] = __shfl_sync(0xffffffffu, acc4[2], base + r);
        ac[4 * r + 3] = __shfl_sync(0xffffffffu, acc4[3], base + r);
    }
    float h4[4];
    #pragma unroll
    for (int j0 = 0; j0 < 4; j0++) h4[j0] = s_pb[jb + j0];
    #pragma unroll
    for (int k = 0; k < 16; k++)
        #pragma unroll
        for (int j0 = 0; j0 < 4; j0++)
            h4[j0] = fmaf(ac[k], s_pw[k * 16 + jb + j0], h4[j0]);

    // scalarize layer-3 message: m3 = relu(h) . l3_w  (partial over 4 comps)
    float z = 0.f;
    #pragma unroll
    for (int j0 = 0; j0 < 4; j0++)
        z = fmaf(fmaxf(h4[j0], 0.f), s_l3w[jb + j0], z);
    z += __shfl_xor_sync(0xffffffffu, z, 1);
    z += __shfl_xor_sync(0xffffffffu, z, 2);
    if (l4 == 0) g_M3[i] = z;
}

// ---------------- fused layer 3: scalar-message gather + sigmoid ----------
// 4 lanes per node; edges split across lanes (consecutive CSR entries per
// group -> coalesced index reads). m3 is 2MB -> fully L2-resident.
__global__ void fused3_kernel(const float* __restrict__ lb,
                              const float* __restrict__ rw,
                              float* __restrict__ out) {
    __shared__ float s_rw[16], s_lb;
    int t = threadIdx.x;
    if (t < 16) s_rw[t] = rw[t];
    if (t == 0) s_lb = lb[0];
    __syncthreads();

    int g  = t >> 2;
    int l4 = t & 3;
    int i  = blockIdx.x * 64 + g;
    if (i >= N_NODES) return;

    int beg = g_ROW[i], end = g_ROW[i + 1];
    float z = 0.f, z2 = 0.f;
    int e = beg + l4;
    for (; e + 4 < end; e += 8) {
        z  += g_M3[__ldg(&g_CSR[e])];
        z2 += g_M3[__ldg(&g_CSR[e + 4])];
    }
    if (e < end) z += g_M3[__ldg(&g_CSR[e])];
    z += z2;

    // root term: each lane handles 4 components
    float4 X = *(const float4*)(g_X2 + 16 * (size_t)i + 4 * l4);
    int jb = 4 * l4;
    z = fmaf(X.x, s_rw[jb + 0], z);
    z = fmaf(X.y, s_rw[jb + 1], z);
    z = fmaf(X.z, s_rw[jb + 2], z);
    z = fmaf(X.w, s_rw[jb + 3], z);

    z += __shfl_xor_sync(0xffffffffu, z, 1);
    z += __shfl_xor_sync(0xffffffffu, z, 2);

    if (l4 == 0) out[i] = 1.f / (1.f + expf(-(z + s_lb)));
}

// ---------------- launch ----------------
extern "C" void kernel_launch(void* const* d_in, const int* in_sizes, int n_in,
                              void* d_out, int out_size) {
    const float* x   = (const float*)d_in[0];
    const void*  ei  = d_in[1];
    const float* p1w = (const float*)d_in[2];
    const float* p1b = (const float*)d_in[3];
    const float* l1w = (const float*)d_in[4];
    const float* l1b = (const float*)d_in[5];
    const float* r1w = (const float*)d_in[6];
    const float* p2w = (const float*)d_in[7];
    const float* p2b = (const float*)d_in[8];
    const float* l2w = (const float*)d_in[9];
    const float* l2b = (const float*)d_in[10];
    const float* r2w = (const float*)d_in[11];
    const float* p3w = (const float*)d_in[12];
    const float* p3b = (const float*)d_in[13];
    const float* l3w = (const float*)d_in[14];
    const float* l3b = (const float*)d_in[15];
    const float* r3w = (const float*)d_in[16];
    float* out = (float*)d_out;

    void *degp = nullptr, *cntp = nullptr, *rowp = nullptr;
    cudaGetSymbolAddress(&degp, g_DEG);
    cudaGetSymbolAddress(&cntp, g_CNT);
    cudaGetSymbolAddress(&rowp, g_ROW);

    const int TB = 256;
    int gridE = (N_EDGES + TB - 1) / TB;
    int gridN = (N_NODES + TB - 1) / TB;
    int gridN4 = (N_NODES * 4 + TB - 1) / TB;   // 4 lanes per node

    // CSR build
    detect_kernel<<<1, 32>>>((const int*)ei);
    cudaMemsetAsync(degp, 0, (size_t)N_NODES * sizeof(int));
    hist_kernel<<<gridE, TB>>>(ei);
    scan1_kernel<<<NSEG, SCAN_T>>>();
    scan2_kernel<<<1, SCAN_T>>>();
    scan3_kernel<<<NSEG, SCAN_T>>>();
    cudaMemcpyAsync(cntp, rowp, (size_t)N_NODES * sizeof(int),
                    cudaMemcpyDeviceToDevice);
    fill_kernel<<<gridE, TB>>>(ei);

    // layers
    pre_kernel<<<gridN, TB>>>(x, p1w, p1b);
    fused1_kernel<<<gridN, TB>>>(x, l1w, l1b, r1w, p2w, p2b);
    fused2_kernel<<<gridN4, TB>>>(l2w, l2b, r2w, p3w, p3b, l3w);
    fused3_kernel<<<gridN4, TB>>>(l3b, r3w, out);
}

// round 9
// speedup vs baseline: 3.5848x; 1.0140x over previous
#include <cuda_runtime.h>
#include <math.h>

#define N_NODES 500000
#define N_EDGES 5000000

#define SCAN_T 256
#define SCAN_I 8
#define SEG (SCAN_T * SCAN_I)                 // 2048
#define NSEG ((N_NODES + SEG - 1) / SEG)      // 245

// ---------------- scratch (device globals: allocation-free) ----------------
__device__ float g_HP [N_NODES * 4];    // layer-1 messages (fp32, padded to 4)
__device__ float g_H  [N_NODES * 16];   // layer-2 messages (fp32)
__device__ float g_M3 [N_NODES];        // layer-3 scalar messages: h3 . l3_w
__device__ float g_X1 [N_NODES * 16];   // layer-1 output
__device__ float g_X2 [N_NODES * 16];   // layer-2 output
__device__ int   g_CSR[N_EDGES];        // src indices sorted by dst
__device__ int   g_ROW[N_NODES + 1];    // CSR row offsets
__device__ int   g_DEG[N_NODES];
__device__ int   g_CNT[N_NODES];        // running fill cursor (init = ROW)
__device__ int   g_BSUM[NSEG];
__device__ int   g_IS64;

// ---------------- clear DEG + index dtype detection (fused) ----------------
__global__ void clear_detect_kernel(const int* __restrict__ p) {
    int i = blockIdx.x * blockDim.x + threadIdx.x;
    if (i < N_NODES) g_DEG[i] = 0;
    if (i == 0) {
        int is64 = 1;
        #pragma unroll 1
        for (int k = 0; k < 64; k++)
            if (p[2 * k + 1] != 0) { is64 = 0; break; }
        g_IS64 = is64;
    }
}

// histogram of dst degrees; 2 edges per thread, vector loads
__global__ void hist_kernel(const void* __restrict__ ei) {
    int q = blockIdx.x * blockDim.x + threadIdx.x;
    if (q >= N_EDGES / 2) return;
    int d0, d1;
    if (g_IS64) {
        const longlong2* p = (const longlong2*)((const long long*)ei + N_EDGES);
        longlong2 u = p[q];
        d0 = (int)u.x; d1 = (int)u.y;
    } else {
        const int2* p = (const int2*)((const int*)ei + N_EDGES);
        int2 u = p[q];
        d0 = u.x; d1 = u.y;
    }
    atomicAdd(&g_DEG[d0], 1);
    atomicAdd(&g_DEG[d1], 1);
}

// ---------------- scan pass 1: per-segment reduce --------------------------
__global__ void scan1_kernel() {
    __shared__ int sm[SCAN_T];
    int t = threadIdx.x;
    int base = blockIdx.x * SEG + t * SCAN_I;
    int sum = 0;
    #pragma unroll
    for (int k = 0; k < SCAN_I; k++) {
        int i = base + k;
        if (i < N_NODES) sum += g_DEG[i];
    }
    sm[t] = sum;
    __syncthreads();
    for (int off = SCAN_T / 2; off > 0; off >>= 1) {
        if (t < off) sm[t] += sm[t + off];
        __syncthreads();
    }
    if (t == 0) g_BSUM[blockIdx.x] = sm[0];
}

// ---------------- scan pass 2 (merged): block offset + local scan ----------
// Each block computes its own exclusive segment offset by reducing
// BSUM[0..bid), then writes g_ROW AND g_CNT for its 2048 nodes.
__global__ void scan23_kernel() {
    __shared__ int sm[SCAN_T];
    int t = threadIdx.x;

    // exclusive offset of this segment
    int v = (t < NSEG && t < blockIdx.x) ? g_BSUM[t] : 0;
    sm[t] = v;
    __syncthreads();
    for (int off = SCAN_T / 2; off > 0; off >>= 1) {
        if (t < off) sm[t] += sm[t + off];
        __syncthreads();
    }
    int boff = sm[0];
    __syncthreads();

    // local inclusive scan over per-thread degree sums
    int base = blockIdx.x * SEG + t * SCAN_I;
    int deg[SCAN_I];
    int tsum = 0;
    #pragma unroll
    for (int k = 0; k < SCAN_I; k++) {
        int i = base + k;
        deg[k] = (i < N_NODES) ? g_DEG[i] : 0;
        tsum += deg[k];
    }
    sm[t] = tsum;
    __syncthreads();
    for (int off = 1; off < SCAN_T; off <<= 1) {
        int x = (t >= off) ? sm[t - off] : 0;
        __syncthreads();
        sm[t] += x;
        __syncthreads();
    }
    int run = boff + sm[t] - tsum;
    #pragma unroll
    for (int k = 0; k < SCAN_I; k++) {
        int i = base + k;
        if (i < N_NODES) { g_ROW[i] = run; g_CNT[i] = run; }
        run += deg[k];
    }
    if (blockIdx.x == 0 && t == 0) g_ROW[N_NODES] = N_EDGES;
}

// fill CSR directly from edge_index; 2 edges per thread, vector loads
__global__ void fill_kernel(const void* __restrict__ ei) {
    int q = blockIdx.x * blockDim.x + threadIdx.x;
    if (q >= N_EDGES / 2) return;
    int s0, s1, d0, d1;
    if (g_IS64) {
        const longlong2* ps = (const longlong2*)ei;
        const longlong2* pd = (const longlong2*)((const long long*)ei + N_EDGES);
        longlong2 us = ps[q];
        longlong2 ud = pd[q];
        s0 = (int)us.x; s1 = (int)us.y;
        d0 = (int)ud.x; d1 = (int)ud.y;
    } else {
        const int2* ps = (const int2*)ei;
        const int2* pd = (const int2*)((const int*)ei + N_EDGES);
        int2 us = ps[q];
        int2 ud = pd[q];
        s0 = us.x; s1 = us.y;
        d0 = ud.x; d1 = ud.y;
    }
    int p0 = atomicAdd(&g_CNT[d0], 1);
    g_CSR[p0] = s0;
    int p1 = atomicAdd(&g_CNT[d1], 1);
    g_CSR[p1] = s1;
}

// ---------------- layer-1 projection (din=3), padded to stride 4 ----------
__global__ void pre_kernel(const float* __restrict__ x,
                           const float* __restrict__ pw,
                           const float* __restrict__ pb) {
    __shared__ float sw[9], sb[3];
    int t = threadIdx.x;
    if (t < 9) sw[t] = pw[t];
    if (t < 3) sb[t] = pb[t];
    __syncthreads();
    int i = blockIdx.x * blockDim.x + t;
    if (i >= N_NODES) return;
    float x0 = x[3 * i + 0], x1 = x[3 * i + 1], x2 = x[3 * i + 2];
    float h0 = fmaxf(fmaf(x0, sw[0], fmaf(x1, sw[3], fmaf(x2, sw[6], sb[0]))), 0.f);
    float h1 = fmaxf(fmaf(x0, sw[1], fmaf(x1, sw[4], fmaf(x2, sw[7], sb[1]))), 0.f);
    float h2 = fmaxf(fmaf(x0, sw[2], fmaf(x1, sw[5], fmaf(x2, sw[8], sb[2]))), 0.f);
    *(float4*)(g_HP + 4 * (size_t)i) = make_float4(h0, h1, h2, 0.f);
}

// ---------------- fused layer 1: gather-agg + update + project-2 ----------
__global__ void fused1_kernel(const float* __restrict__ x,
                              const float* __restrict__ lw,
                              const float* __restrict__ lb,
                              const float* __restrict__ rw,
                              const float* __restrict__ pw,
                              const float* __restrict__ pb) {
    __shared__ float s_lw[48], s_rw[48], s_lb[16], s_pw[256], s_pb[16];
    int t = threadIdx.x;
    if (t < 48) { s_lw[t] = lw[t]; s_rw[t] = rw[t]; }
    if (t < 16) { s_lb[t] = lb[t]; s_pb[t] = pb[t]; }
    s_pw[t] = pw[t];
    __syncthreads();
    int i = blockIdx.x * blockDim.x + t;
    if (i >= N_NODES) return;

    int beg = g_ROW[i], end = g_ROW[i + 1];
    float a0 = 0.f, a1 = 0.f, a2 = 0.f;
    float b0 = 0.f, b1 = 0.f, b2 = 0.f;
    int e = beg;
    for (; e + 3 < end; e += 4) {
        int s0 = __ldg(&g_CSR[e]),     s1 = __ldg(&g_CSR[e + 1]);
        int s2 = __ldg(&g_CSR[e + 2]), s3 = __ldg(&g_CSR[e + 3]);
        float4 v0 = *(const float4*)(g_HP + 4 * (size_t)s0);
        float4 v1 = *(const float4*)(g_HP + 4 * (size_t)s1);
        float4 v2 = *(const float4*)(g_HP + 4 * (size_t)s2);
        float4 v3 = *(const float4*)(g_HP + 4 * (size_t)s3);
        a0 += v0.x + v1.x; a1 += v0.y + v1.y; a2 += v0.z + v1.z;
        b0 += v2.x + v3.x; b1 += v2.y + v3.y; b2 += v2.z + v3.z;
    }
    for (; e < end; e++) {
        float4 v = *(const float4*)(g_HP + 4 * (size_t)__ldg(&g_CSR[e]));
        a0 += v.x; a1 += v.y; a2 += v.z;
    }
    a0 += b0; a1 += b1; a2 += b2;

    float x0 = x[3 * i + 0], x1 = x[3 * i + 1], x2 = x[3 * i + 2];
    float acc[16];
    #pragma unroll
    for (int j = 0; j < 16; j++) {
        float v = s_lb[j];
        v = fmaf(a0, s_lw[j],      fmaf(x0, s_rw[j],      v));
        v = fmaf(a1, s_lw[16 + j], fmaf(x1, s_rw[16 + j], v));
        v = fmaf(a2, s_lw[32 + j], fmaf(x2, s_rw[32 + j], v));
        acc[j] = fmaxf(v, 0.f);
    }

    float4* xo = (float4*)(g_X1 + 16 * (size_t)i);
    xo[0] = make_float4(acc[0], acc[1], acc[2], acc[3]);
    xo[1] = make_float4(acc[4], acc[5], acc[6], acc[7]);
    xo[2] = make_float4(acc[8], acc[9], acc[10], acc[11]);
    xo[3] = make_float4(acc[12], acc[13], acc[14], acc[15]);

    float h[16];
    #pragma unroll
    for (int j = 0; j < 16; j++) h[j] = s_pb[j];
    #pragma unroll
    for (int k = 0; k < 16; k++)
        #pragma unroll
        for (int j = 0; j < 16; j++)
            h[j] = fmaf(acc[k], s_pw[k * 16 + j], h[j]);
    float4* ho = (float4*)(g_H + 16 * (size_t)i);
    ho[0] = make_float4(fmaxf(h[0], 0.f),  fmaxf(h[1], 0.f),  fmaxf(h[2], 0.f),  fmaxf(h[3], 0.f));
    ho[1] = make_float4(fmaxf(h[4], 0.f),  fmaxf(h[5], 0.f),  fmaxf(h[6], 0.f),  fmaxf(h[7], 0.f));
    ho[2] = make_float4(fmaxf(h[8], 0.f),  fmaxf(h[9], 0.f),  fmaxf(h[10], 0.f), fmaxf(h[11], 0.f));
    ho[3] = make_float4(fmaxf(h[12], 0.f), fmaxf(h[13], 0.f), fmaxf(h[14], 0.f), fmaxf(h[15], 0.f));
}

// ---------------- fused layer 2: 4 lanes per node -------------------------
__global__ void fused2_kernel(const float* __restrict__ lw,
                              const float* __restrict__ lb,
                              const float* __restrict__ rw,
                              const float* __restrict__ pw,
                              const float* __restrict__ pb,
                              const float* __restrict__ l3w) {
    __shared__ float s_lw[256], s_rw[256], s_lb[16], s_pw[256], s_pb[16], s_l3w[16];
    int t = threadIdx.x;
    s_lw[t] = lw[t]; s_rw[t] = rw[t]; s_pw[t] = pw[t];
    if (t < 16) { s_lb[t] = lb[t]; s_pb[t] = pb[t]; s_l3w[t] = l3w[t]; }
    __syncthreads();

    int g  = t >> 2;          // node group within block (0..63)
    int l4 = t & 3;           // lane within group
    int i  = blockIdx.x * 64 + g;
    if (i >= N_NODES) return;

    int lane = t & 31;
    int base = lane & ~3;

    int beg = g_ROW[i], end = g_ROW[i + 1];
    float4 A = make_float4(0.f, 0.f, 0.f, 0.f);
    float4 B = make_float4(0.f, 0.f, 0.f, 0.f);
    int e = beg;
    for (; e + 1 < end; e += 2) {
        int s0 = __ldg(&g_CSR[e]);
        int s1 = __ldg(&g_CSR[e + 1]);
        float4 v0 = *(const float4*)(g_H + 16 * (size_t)s0 + 4 * l4);
        float4 v1 = *(const float4*)(g_H + 16 * (size_t)s1 + 4 * l4);
        A.x += v0.x; A.y += v0.y; A.z += v0.z; A.w += v0.w;
        B.x += v1.x; B.y += v1.y; B.z += v1.z; B.w += v1.w;
    }
    if (e < end) {
        float4 v = *(const float4*)(g_H + 16 * (size_t)__ldg(&g_CSR[e]) + 4 * l4);
        A.x += v.x; A.y += v.y; A.z += v.z; A.w += v.w;
    }
    A.x += B.x; A.y += B.y; A.z += B.z; A.w += B.w;

    float4 X = *(const float4*)(g_X1 + 16 * (size_t)i + 4 * l4);

    float a[16], xr[16];
    #pragma unroll
    for (int r = 0; r < 4; r++) {
        a[4 * r + 0]  = __shfl_sync(0xffffffffu, A.x, base + r);
        a[4 * r + 1]  = __shfl_sync(0xffffffffu, A.y, base + r);
        a[4 * r + 2]  = __shfl_sync(0xffffffffu, A.z, base + r);
        a[4 * r + 3]  = __shfl_sync(0xffffffffu, A.w, base + r);
        xr[4 * r + 0] = __shfl_sync(0xffffffffu, X.x, base + r);
        xr[4 * r + 1] = __shfl_sync(0xffffffffu, X.y, base + r);
        xr[4 * r + 2] = __shfl_sync(0xffffffffu, X.z, base + r);
        xr[4 * r + 3] = __shfl_sync(0xffffffffu, X.w, base + r);
    }

    int jb = 4 * l4;
    float acc4[4];
    #pragma unroll
    for (int j0 = 0; j0 < 4; j0++) acc4[j0] = s_lb[jb + j0];
    #pragma unroll
    for (int k = 0; k < 16; k++)
        #pragma unroll
        for (int j0 = 0; j0 < 4; j0++)
            acc4[j0] = fmaf(a[k], s_lw[k * 16 + jb + j0],
                       fmaf(xr[k], s_rw[k * 16 + jb + j0], acc4[j0]));
    #pragma unroll
    for (int j0 = 0; j0 < 4; j0++) acc4[j0] = fmaxf(acc4[j0], 0.f);

    *(float4*)(g_X2 + 16 * (size_t)i + jb) =
        make_float4(acc4[0], acc4[1], acc4[2], acc4[3]);

    float ac[16];
    #pragma unroll
    for (int r = 0; r < 4; r++) {
        ac[4 * r + 0] = __shfl_sync(0xffffffffu, acc4[0], base + r);
        ac[4 * r + 1] = __shfl_sync(0xffffffffu, acc4[1], base + r);
        ac[4 * r + 2] = __shfl_sync(0xffffffffu, acc4[2], base + r);
        ac[4 * r + 3] = __shfl_sync(0xffffffffu, acc4[3], base + r);
    }
    float h4[4];
    #pragma unroll
    for (int j0 = 0; j0 < 4; j0++) h4[j0] = s_pb[jb + j0];
    #pragma unroll
    for (int k = 0; k < 16; k++)
        #pragma unroll
        for (int j0 = 0; j0 < 4; j0++)
            h4[j0] = fmaf(ac[k], s_pw[k * 16 + jb + j0], h4[j0]);

    // scalarize layer-3 message: m3 = relu(h) . l3_w
    float z = 0.f;
    #pragma unroll
    for (int j0 = 0; j0 < 4; j0++)
        z = fmaf(fmaxf(h4[j0], 0.f), s_l3w[jb + j0], z);
    z += __shfl_xor_sync(0xffffffffu, z, 1);
    z += __shfl_xor_sync(0xffffffffu, z, 2);
    if (l4 == 0) g_M3[i] = z;
}

// ---------------- fused layer 3: scalar-message gather + sigmoid ----------
__global__ void fused3_kernel(const float* __restrict__ lb,
                              const float* __restrict__ rw,
                              float* __restrict__ out) {
    __shared__ float s_rw[16], s_lb;
    int t = threadIdx.x;
    if (t < 16) s_rw[t] = rw[t];
    if (t == 0) s_lb = lb[0];
    __syncthreads();

    int g  = t >> 2;
    int l4 = t & 3;
    int i  = blockIdx.x * 64 + g;
    if (i >= N_NODES) return;

    int beg = g_ROW[i], end = g_ROW[i + 1];
    float z = 0.f, z2 = 0.f;
    int e = beg + l4;
    for (; e + 4 < end; e += 8) {
        z  += g_M3[__ldg(&g_CSR[e])];
        z2 += g_M3[__ldg(&g_CSR[e + 4])];
    }
    if (e < end) z += g_M3[__ldg(&g_CSR[e])];
    z += z2;

    float4 X = *(const float4*)(g_X2 + 16 * (size_t)i + 4 * l4);
    int jb = 4 * l4;
    z = fmaf(X.x, s_rw[jb + 0], z);
    z = fmaf(X.y, s_rw[jb + 1], z);
    z = fmaf(X.z, s_rw[jb + 2], z);
    z = fmaf(X.w, s_rw[jb + 3], z);

    z += __shfl_xor_sync(0xffffffffu, z, 1);
    z += __shfl_xor_sync(0xffffffffu, z, 2);

    if (l4 == 0) out[i] = 1.f / (1.f + expf(-(z + s_lb)));
}

// ---------------- launch ----------------
extern "C" void kernel_launch(void* const* d_in, const int* in_sizes, int n_in,
                              void* d_out, int out_size) {
    const float* x   = (const float*)d_in[0];
    const void*  ei  = d_in[1];
    const float* p1w = (const float*)d_in[2];
    const float* p1b = (const float*)d_in[3];
    const float* l1w = (const float*)d_in[4];
    const float* l1b = (const float*)d_in[5];
    const float* r1w = (const float*)d_in[6];
    const float* p2w = (const float*)d_in[7];
    const float* p2b = (const float*)d_in[8];
    const float* l2w = (const float*)d_in[9];
    const float* l2b = (const float*)d_in[10];
    const float* r2w = (const float*)d_in[11];
    const float* p3w = (const float*)d_in[12];
    const float* p3b = (const float*)d_in[13];
    const float* l3w = (const float*)d_in[14];
    const float* l3b = (const float*)d_in[15];
    const float* r3w = (const float*)d_in[16];
    float* out = (float*)d_out;

    const int TB = 256;
    int gridE2 = (N_EDGES / 2 + TB - 1) / TB;   // 2 edges per thread
    int gridN  = (N_NODES + TB - 1) / TB;
    int gridN4 = (N_NODES * 4 + TB - 1) / TB;   // 4 lanes per node

    // CSR build (5 launches)
    clear_detect_kernel<<<gridN, TB>>>((const int*)ei);
    hist_kernel<<<gridE2, TB>>>(ei);
    scan1_kernel<<<NSEG, SCAN_T>>>();
    scan23_kernel<<<NSEG, SCAN_T>>>();
    fill_kernel<<<gridE2, TB>>>(ei);

    // layers (4 launches)
    pre_kernel<<<gridN, TB>>>(x, p1w, p1b);
    fused1_kernel<<<gridN, TB>>>(x, l1w, l1b, r1w, p2w, p2b);
    fused2_kernel<<<gridN4, TB>>>(l2w, l2b, r2w, p3w, p3b, l3w);
    fused3_kernel<<<gridN4, TB>>>(l3b, r3w, out);
}